// round 17
// baseline (speedup 1.0000x reference)
#include <cuda_runtime.h>
#include <cuda_fp16.h>
#include <math.h>
#include <stdint.h>

// Problem constants
#define B_   4
#define T_   4096
#define D_   1024
#define H_   16
#define HD   64
#define BT   (B_*T_)      // 16384
#define BH   (B_*H_)      // 64
#define NKV  3072
#define NCHUNK 32
#define CHLEN (T_/NCHUNK) // 128
#define GK   1024

// Scratch
__device__ __half g_xh  [BT*D_];     // x in fp16
__device__ __half g_qfh [BH*T_*HD];  // q feature map, fp16
__device__ __half g_kfh [BH*T_*HD];  // k feature map, fp16
__device__ __half g_vh  [BH*T_*HD];  // v, fp16
__device__ float  g_kvp [NCHUNK*BH*HD*HD];   // fp32 partials
__device__ __half g_kvTh[BH*HD*HD];  // kv transposed [bh][j][d], fp16
__device__ float  g_ksp [NCHUNK*BH*HD];
__device__ float  g_ksum[BH*HD];
__device__ __half g_attnh[BT*D_];    // attn output, fp16 (feeds GEMM2)
__device__ __half g_wqTh[NKV*D_];    // Wqkv^T fp16
__device__ __half g_woTh[D_*D_];     // Wout^T fp16
__device__ float  g_cos[T_*32];
__device__ float  g_sin[T_*32];

// ---------------------------------------------------------------------------
__device__ __forceinline__ uint32_t smem_u32(const void* p) {
    uint32_t a;
    asm("{ .reg .u64 t; cvta.to.shared.u64 t, %1; cvt.u32.u64 %0, t; }"
        : "=r"(a) : "l"(p));
    return a;
}
#define CP_ASYNC16(dst, src) \
    asm volatile("cp.async.cg.shared.global [%0], [%1], 16;" :: "r"(dst), "l"(src) : "memory")
#define CP_COMMIT()  asm volatile("cp.async.commit_group;" ::: "memory")
#define CP_WAIT2()   asm volatile("cp.async.wait_group 2;" ::: "memory")

__device__ __forceinline__ void ldsm_x4(uint32_t* r, uint32_t addr) {
    asm volatile("ldmatrix.sync.aligned.m8n8.x4.shared.b16 {%0,%1,%2,%3}, [%4];"
        : "=r"(r[0]), "=r"(r[1]), "=r"(r[2]), "=r"(r[3]) : "r"(addr));
}
__device__ __forceinline__ void ldsm_x4_t(uint32_t* r, uint32_t addr) {
    asm volatile("ldmatrix.sync.aligned.m8n8.x4.trans.shared.b16 {%0,%1,%2,%3}, [%4];"
        : "=r"(r[0]), "=r"(r[1]), "=r"(r[2]), "=r"(r[3]) : "r"(addr));
}
// fp16 MMA: m16n8k16, fp32 accumulate
__device__ __forceinline__ void mma_f16(float* d, const uint32_t* a, const uint32_t* b) {
    asm volatile(
        "mma.sync.aligned.m16n8k16.row.col.f32.f16.f16.f32 "
        "{%0,%1,%2,%3}, {%4,%5,%6,%7}, {%8,%9}, {%0,%1,%2,%3};"
        : "+f"(d[0]), "+f"(d[1]), "+f"(d[2]), "+f"(d[3])
        : "r"(a[0]), "r"(a[1]), "r"(a[2]), "r"(a[3]),
          "r"(b[0]), "r"(b[1]));
}
__device__ __forceinline__ float elu1(float x) {
    return x > 0.f ? x + 1.f : expf(x);
}
__device__ __forceinline__ uint32_t pack_h2(float a, float b) {
    __half2 h = __floats2half2_rn(a, b);
    return *(uint32_t*)&h;
}

// ---------------------------------------------------------------------------
// fp16 mma.sync GEMM (R16 config): 128x128 CTA, BK=32 halfs, 4-stage cp.async,
// 256 threads, warp tile 32x64, anti-phase k16 halves, mid-iteration prefetch.
// mode 0: plain fp32 C store. mode 1: fused RoPE/elu qkv epilogue (fp16 out).
// ---------------------------------------------------------------------------
#define STAGES 4
#define ROWH   40
#define STG_H  (128*ROWH)
#define GEMM_SMEM (2*STAGES*STG_H*2)    // 81920 B

__global__ __launch_bounds__(256, 2)
void gemm_f16_kernel(int N, int mode, const __half* __restrict__ A,
                     const __half* __restrict__ Bt, float* __restrict__ C) {
    extern __shared__ __half smh[];
    __half* As = smh;
    __half* Bs = smh + STAGES*STG_H;

    const int tid  = threadIdx.x;
    const int wid  = tid >> 5;
    const int lane = tid & 31;
    const int g    = lane >> 2;
    const int tg   = lane & 3;
    const int lrow = lane & 7;
    const int seg  = lane >> 3;      // 0..3

    const int rowBase = blockIdx.y * 128;
    const int colBase = blockIdx.x * 128;
    const int mBase = (wid & 3) * 32;
    const int nBase = (wid >> 2) * 64;

    const int crow = tid & 127;
    const int s0   = tid >> 7;
    const __half* aSrc = A  + (size_t)(rowBase + crow)*GK;
    const __half* bSrc = Bt + (size_t)(colBase + crow)*GK;
    const uint32_t aDst = smem_u32(As) + (uint32_t)(crow*ROWH)*2;
    const uint32_t bDst = smem_u32(Bs) + (uint32_t)(crow*ROWH)*2;

    const uint32_t aFrag0 = smem_u32(As) +
        (uint32_t)(((mBase + (seg & 1)*8 + lrow)*ROWH + (seg >> 1)*8) * 2);
    const uint32_t bFrag0 = smem_u32(Bs) +
        (uint32_t)(((nBase + (seg >> 1)*8 + lrow)*ROWH + (seg & 1)*8) * 2);

    const uint32_t ksA = (wid & 1) ? 32u : 0u;
    const uint32_t ksB = ksA ^ 32u;

    float acc[2][8][4];
    #pragma unroll
    for (int mt = 0; mt < 2; mt++)
        #pragma unroll
        for (int nt = 0; nt < 8; nt++)
            #pragma unroll
            for (int q = 0; q < 4; q++) acc[mt][nt][q] = 0.f;

    #pragma unroll
    for (int s = 0; s < STAGES-1; s++) {
        const uint32_t so = (uint32_t)s * (STG_H*2);
        const __half* ap = aSrc + s*32;
        const __half* bp = bSrc + s*32;
        CP_ASYNC16(aDst + so + 16*s0,      ap + 8*s0);
        CP_ASYNC16(aDst + so + 16*(s0+2),  ap + 8*(s0+2));
        CP_ASYNC16(bDst + so + 16*s0,      bp + 8*s0);
        CP_ASYNC16(bDst + so + 16*(s0+2),  bp + 8*(s0+2));
        CP_COMMIT();
    }

    const int NIT = GK / 32;   // 32
    for (int it = 0; it < NIT; it++) {
        CP_WAIT2();
        __syncthreads();

        const uint32_t so = (uint32_t)(it % STAGES) * (STG_H*2);
        const uint32_t aF = aFrag0 + so;
        const uint32_t bF = bFrag0 + so;

        {
            uint32_t af[2][4], bf[4][4];
            ldsm_x4(af[0], aF             + ksA);
            ldsm_x4(af[1], aF + 16*ROWH*2 + ksA);
            #pragma unroll
            for (int p = 0; p < 4; p++)
                ldsm_x4(bf[p], bF + p*16*ROWH*2 + ksA);
            #pragma unroll
            for (int mt = 0; mt < 2; mt++)
                #pragma unroll
                for (int nt = 0; nt < 8; nt++)
                    mma_f16(acc[mt][nt], af[mt], &bf[nt >> 1][(nt & 1)*2]);
        }

        const int nit = it + STAGES - 1;
        if (nit < NIT) {
            const int s = nit % STAGES;
            const uint32_t po = (uint32_t)s * (STG_H*2);
            const __half* ap = aSrc + nit*32;
            const __half* bp = bSrc + nit*32;
            CP_ASYNC16(aDst + po + 16*s0,      ap + 8*s0);
            CP_ASYNC16(aDst + po + 16*(s0+2),  ap + 8*(s0+2));
            CP_ASYNC16(bDst + po + 16*s0,      bp + 8*s0);
            CP_ASYNC16(bDst + po + 16*(s0+2),  bp + 8*(s0+2));
        }
        CP_COMMIT();

        {
            uint32_t af[2][4], bf[4][4];
            ldsm_x4(af[0], aF             + ksB);
            ldsm_x4(af[1], aF + 16*ROWH*2 + ksB);
            #pragma unroll
            for (int p = 0; p < 4; p++)
                ldsm_x4(bf[p], bF + p*16*ROWH*2 + ksB);
            #pragma unroll
            for (int mt = 0; mt < 2; mt++)
                #pragma unroll
                for (int nt = 0; nt < 8; nt++)
                    mma_f16(acc[mt][nt], af[mt], &bf[nt >> 1][(nt & 1)*2]);
        }
    }

    if (mode == 0) {
        #pragma unroll
        for (int mt = 0; mt < 2; mt++) {
            const int r0 = rowBase + mBase + mt*16 + g;
            #pragma unroll
            for (int nt = 0; nt < 8; nt++) {
                const int c0 = colBase + nBase + nt*8 + tg*2;
                *(float2*)&C[(size_t) r0   *N + c0] = make_float2(acc[mt][nt][0], acc[mt][nt][1]);
                *(float2*)&C[(size_t)(r0+8)*N + c0] = make_float2(acc[mt][nt][2], acc[mt][nt][3]);
            }
        }
    } else {
        // fused qkv epilogue: all three outputs stored fp16
        const int region = colBase >> 10;            // 0=q 1=k 2=v
        __half* dst = (region == 0) ? g_qfh : (region == 1 ? g_kfh : g_vh);
        const int head = (((colBase & 1023) + nBase) >> 6);
        #pragma unroll
        for (int mt = 0; mt < 2; mt++) {
            #pragma unroll
            for (int half_ = 0; half_ < 2; half_++) {
                const int row = rowBase + mBase + mt*16 + g + half_*8;
                const int t = row & (T_-1);
                const int b = row >> 12;
                const size_t obase = ((size_t)(b*H_ + head)*T_ + t)*HD;
                #pragma unroll
                for (int nt = 0; nt < 4; nt++) {
                    const int i0 = nt*8 + tg*2;
                    const float a0 = acc[mt][nt  ][half_*2+0];
                    const float a1 = acc[mt][nt  ][half_*2+1];
                    const float b0 = acc[mt][nt+4][half_*2+0];
                    const float b1 = acc[mt][nt+4][half_*2+1];
                    if (region == 2) {
                        *(uint32_t*)&dst[obase + i0]      = pack_h2(a0, a1);
                        *(uint32_t*)&dst[obase + i0 + 32] = pack_h2(b0, b1);
                    } else {
                        const float2 cc = *(const float2*)&g_cos[t*32 + i0];
                        const float2 ss = *(const float2*)&g_sin[t*32 + i0];
                        float r10 = a0*cc.x - b0*ss.x, r20 = b0*cc.x + a0*ss.x;
                        float r11 = a1*cc.y - b1*ss.y, r21 = b1*cc.y + a1*ss.y;
                        if (region == 0) {
                            r10 *= 0.125f; r20 *= 0.125f; r11 *= 0.125f; r21 *= 0.125f;
                        }
                        *(uint32_t*)&dst[obase + i0]      = pack_h2(elu1(r10), elu1(r11));
                        *(uint32_t*)&dst[obase + i0 + 32] = pack_h2(elu1(r20), elu1(r21));
                    }
                }
            }
        }
    }
}

// ---------------------------------------------------------------------------
// merged prep: blocks [0, XH_BLOCKS) convert x->fp16; rest build RoPE tables
// ---------------------------------------------------------------------------
#define XH_BLOCKS (BT*D_/4/256)     // 16384
#define RT_BLOCKS (T_*32/256)       // 512

__global__ __launch_bounds__(256)
void prep_kernel(const float* __restrict__ x) {
    if (blockIdx.x < XH_BLOCKS) {
        int i = blockIdx.x * 256 + threadIdx.x;
        float4 v = ((const float4*)x)[i];
        uint2 o;
        o.x = pack_h2(v.x, v.y);
        o.y = pack_h2(v.z, v.w);
        ((uint2*)g_xh)[i] = o;
    } else {
        int idx = (blockIdx.x - XH_BLOCKS) * 256 + threadIdx.x;
        int t = idx >> 5;
        int i = idx & 31;
        float inv = powf(500000.0f, -(float)i * (1.0f/32.0f));
        float a = (float)t * inv;
        g_cos[idx] = cosf(a);
        g_sin[idx] = sinf(a);
    }
}

// both weight transposes (fp32 -> fp16) in ONE launch
__global__ __launch_bounds__(256)
void transpose_half_kernel(const float* __restrict__ wq, const float* __restrict__ wo) {
    __shared__ float tile[32][33];
    const int R = D_;
    const float* in; __half* out; int Cc; int bx;
    if (blockIdx.x < NKV/32) { in = wq; out = g_wqTh; Cc = NKV; bx = blockIdx.x * 32; }
    else                     { in = wo; out = g_woTh; Cc = D_;  bx = (blockIdx.x - NKV/32) * 32; }
    int by = blockIdx.y * 32;
    int tx = threadIdx.x, ty = threadIdx.y;
    #pragma unroll
    for (int i = 0; i < 32; i += 8)
        tile[ty + i][tx] = in[(size_t)(by + ty + i) * Cc + bx + tx];
    __syncthreads();
    #pragma unroll
    for (int i = 0; i < 32; i += 8)
        out[(size_t)(bx + ty + i) * R + by + tx] = __float2half_rn(tile[tx][ty + i]);
}

// ---------------------------------------------------------------------------
// kv partial accumulation — TENSORIZED. Block = (bh, chunk of 128 t).
// C[d][j] = sum_t kf[t][d] * v[t][j]: both operands via ldmatrix.x4.trans
// (source rows = t). 128 threads = 4 warps, warp = m16(d) x n64(j), K=128 in
// 8 k16 steps. fp32 MMA accumulators -> fp32 partials (unchanged reduce).
// ksum via scalar fp32 pass over the smem kf tile.
// ---------------------------------------------------------------------------
#define ROWK 72
#define KV_SMEM (2*128*ROWK*2)   // 36864 B

__global__ __launch_bounds__(128)
void kv_accum_kernel() {
    extern __shared__ __half smk[];
    __half* kfb = smk;               // [128][ROWK]
    __half* vb  = smk + 128*ROWK;    // [128][ROWK]
    __shared__ float sred[128];

    const int blk = blockIdx.x;
    const int bh  = blk >> 5;
    const int c   = blk & 31;
    const int tid = threadIdx.x;
    const int wid = tid >> 5;
    const int lane = tid & 31;
    const int lrow = lane & 7;
    const int grp  = lane >> 3;      // 0..3

    const int t0 = c * CHLEN;

    // fill both 128x64 fp16 tiles (16B chunks, coalesced)
    #pragma unroll
    for (int u = 0; u < 8; u++) {
        int f  = tid + u*128;        // 0..1023
        int rr = f >> 3, sg = f & 7;
        *(uint4*)&kfb[rr*ROWK + sg*8] =
            *(const uint4*)&g_kfh[((size_t)bh*T_ + t0 + rr)*HD + sg*8];
        *(uint4*)&vb[rr*ROWK + sg*8] =
            *(const uint4*)&g_vh[((size_t)bh*T_ + t0 + rr)*HD + sg*8];
    }
    __syncthreads();

    // ksum: d = tid&63, half th = tid>>6 covers 64 t rows; combine via smem
    {
        const int d  = tid & 63;
        const int th = tid >> 6;
        float s = 0.f;
        #pragma unroll 8
        for (int t = th*64; t < th*64 + 64; t++)
            s += __half2float(kfb[t*ROWK + d]);
        sred[tid] = s;
    }
    __syncthreads();
    if (tid < 64)
        g_ksp[(c*BH + bh)*HD + tid] = sred[tid] + sred[tid + 64];

    // MMA: warp wid owns d rows [wid*16, wid*16+16)
    const int d0 = wid * 16;
    float acc[8][4];
    #pragma unroll
    for (int nt = 0; nt < 8; nt++)
        #pragma unroll
        for (int q = 0; q < 4; q++) acc[nt][q] = 0.f;

    #pragma unroll
    for (int kk = 0; kk < 8; kk++) {
        const int tt = kk * 16;
        // A fragment (m=d, k=t): matrices {m0,k0},{m8,k0},{m0,k8},{m8,k8}
        // -> group g addresses kf[(tt + (g>>1)*8 + lrow)][d0 + (g&1)*8]
        uint32_t af[4];
        ldsm_x4_t(af, smem_u32(kfb) +
            (uint32_t)(((tt + (grp >> 1)*8 + lrow)*ROWK + d0 + (grp & 1)*8) * 2));
        // B fragments: pair p covers n-tiles 2p,2p+1 (j0 = p*16):
        // matrices {k0,j0},{k8,j0},{k0,j0+8},{k8,j0+8}
        // -> group g addresses v[(tt + (g&1)*8 + lrow)][p*16 + (g>>1)*8]
        #pragma unroll
        for (int p = 0; p < 4; p++) {
            uint32_t bf[4];
            ldsm_x4_t(bf, smem_u32(vb) +
                (uint32_t)(((tt + (grp & 1)*8 + lrow)*ROWK + p*16 + (grp >> 1)*8) * 2));
            mma_f16(acc[2*p    ], af, &bf[0]);
            mma_f16(acc[2*p + 1], af, &bf[2]);
        }
    }

    // store fp32 partials: row d = d0 + lane/4 (+8), col j = nt*8 + (lane&3)*2
    #pragma unroll
    for (int nt = 0; nt < 8; nt++) {
        float* p0 = &g_kvp[((size_t)(c*BH + bh)*HD + d0 + (lane >> 2))*HD + nt*8 + (lane & 3)*2];
        *(float2*)p0 = make_float2(acc[nt][0], acc[nt][1]);
        *(float2*)(p0 + 8*HD) = make_float2(acc[nt][2], acc[nt][3]);
    }
}

// kv reduce -> g_kvTh (transposed fp16) and g_ksum
__global__ void kv_reduce_kernel() {
    if (blockIdx.x < (BH*HD*HD)/256) {
        int idx = blockIdx.x * 256 + threadIdx.x;
        float s = 0.f;
        #pragma unroll
        for (int c = 0; c < NCHUNK; c++) s += g_kvp[(size_t)c*BH*HD*HD + idx];
        int j  = idx & 63;
        int d  = (idx >> 6) & 63;
        int bh = idx >> 12;
        g_kvTh[bh*HD*HD + j*HD + d] = __float2half_rn(s);
    } else {
        int idx = (blockIdx.x - (BH*HD*HD)/256) * 256 + threadIdx.x;
        if (idx < BH*HD) {
            float s = 0.f;
            #pragma unroll
            for (int c = 0; c < NCHUNK; c++) s += g_ksp[c*BH*HD + idx];
            g_ksum[idx] = s;
        }
    }
}

// ---------------------------------------------------------------------------
// attn numerator via fp16 MMA (R16 config, unchanged)
// ---------------------------------------------------------------------------
#define ROWQ 72
#define ATT_SMEM ((192*ROWQ)*2 + (64 + 128)*4)

__global__ __launch_bounds__(128)
void attn_mma_kernel() {
    extern __shared__ __half smq[];
    __half* qa  = smq;                       // [128][ROWQ]
    __half* kvb = smq + 128*ROWQ;            // [64][ROWQ]
    float* sks  = (float*)(smq + 192*ROWQ);  // [64]
    float* sden = sks + 64;                  // [128]

    const int blk = blockIdx.x;
    const int bh  = blk >> 5;
    const int tc  = blk & 31;
    const int b   = bh >> 4;
    const int h   = bh & 15;
    const int tid = threadIdx.x;
    const int wid = tid >> 5;
    const int lane = tid & 31;
    const int g    = lane >> 2;
    const int tg   = lane & 3;
    const int lrow = lane & 7;
    const int seg  = lane >> 3;

    #pragma unroll
    for (int u = 0; u < 8; u++) {
        int f  = tid + u*128;
        int rr = f >> 3, sg = f & 7;
        *(uint4*)&qa[rr*ROWQ + sg*8] =
            *(const uint4*)&g_qfh[((size_t)bh*T_ + tc*128 + rr)*HD + sg*8];
    }
    #pragma unroll
    for (int u = 0; u < 4; u++) {
        int f  = tid + u*128;
        int rr = f >> 3, sg = f & 7;
        *(uint4*)&kvb[rr*ROWQ + sg*8] =
            *(const uint4*)&g_kvTh[bh*HD*HD + rr*HD + sg*8];
    }
    if (tid < 64) sks[tid] = g_ksum[bh*HD + tid];
    __syncthreads();

    {
        float den = 0.f;
        #pragma unroll
        for (int d = 0; d < 32; d++) {
            __half2 q2 = *(const __half2*)&qa[tid*ROWQ + d*2];
            float2 qf2 = __half22float2(q2);
            den += qf2.x * sks[d*2] + qf2.y * sks[d*2+1];
        }
        sden[tid] = 1.f / fmaxf(den, 1e-6f);
    }
    __syncthreads();

    const int mBase = wid * 32;
    const uint32_t aFrag0 = smem_u32(qa) +
        (uint32_t)(((mBase + (seg & 1)*8 + lrow)*ROWQ + (seg >> 1)*8) * 2);
    const uint32_t bFrag0 = smem_u32(kvb) +
        (uint32_t)((((seg >> 1)*8 + lrow)*ROWQ + (seg & 1)*8) * 2);

    float acc[2][8][4];
    #pragma unroll
    for (int mt = 0; mt < 2; mt++)
        #pragma unroll
        for (int nt = 0; nt < 8; nt++)
            #pragma unroll
            for (int q = 0; q < 4; q++) acc[mt][nt][q] = 0.f;

    const int krot = wid & 3;
    #pragma unroll
    for (int kk = 0; kk < 4; kk++) {
        const uint32_t ks = (uint32_t)(((kk + krot) & 3) * 32);
        uint32_t af[2][4];
        uint32_t bf[4][4];
        ldsm_x4(af[0], aFrag0             + ks);
        ldsm_x4(af[1], aFrag0 + 16*ROWQ*2 + ks);
        #pragma unroll
        for (int p = 0; p < 4; p++)
            ldsm_x4(bf[p], bFrag0 + p*16*ROWQ*2 + ks);
        #pragma unroll
        for (int mt = 0; mt < 2; mt++)
            #pragma unroll
            for (int nt = 0; nt < 8; nt++)
                mma_f16(acc[mt][nt], af[mt], &bf[nt >> 1][(nt & 1)*2]);
    }

    #pragma unroll
    for (int mt = 0; mt < 2; mt++) {
        const int rl0 = mBase + mt*16 + g;
        const float s0 = sden[rl0];
        const float s1 = sden[rl0 + 8];
        const int t0 = tc*128 + rl0;
        __half* o0 = &g_attnh[((size_t)(b*T_ + t0    ))*D_ + h*HD];
        __half* o1 = &g_attnh[((size_t)(b*T_ + t0 + 8))*D_ + h*HD];
        #pragma unroll
        for (int nt = 0; nt < 8; nt++) {
            const int c0 = nt*8 + tg*2;
            *(uint32_t*)&o0[c0] = pack_h2(acc[mt][nt][0]*s0, acc[mt][nt][1]*s0);
            *(uint32_t*)&o1[c0] = pack_h2(acc[mt][nt][2]*s1, acc[mt][nt][3]*s1);
        }
    }
}

// ---------------------------------------------------------------------------
extern "C" void kernel_launch(void* const* d_in, const int* in_sizes, int n_in,
                              void* d_out, int out_size) {
    const float* x = nullptr; const float* Wqkv = nullptr; const float* Wout = nullptr;
    for (int i = 0; i < n_in; i++) {
        if (in_sizes[i] == BT*D_)       x    = (const float*)d_in[i];
        else if (in_sizes[i] == D_*NKV) Wqkv = (const float*)d_in[i];
        else if (in_sizes[i] == D_*D_)  Wout = (const float*)d_in[i];
    }
    float* out = (float*)d_out;

    __half *xh_p, *attnh_p, *wqTh_p, *woTh_p;
    cudaGetSymbolAddress((void**)&xh_p,    g_xh);
    cudaGetSymbolAddress((void**)&attnh_p, g_attnh);
    cudaGetSymbolAddress((void**)&wqTh_p,  g_wqTh);
    cudaGetSymbolAddress((void**)&woTh_p,  g_woTh);

    cudaFuncSetAttribute(gemm_f16_kernel,
                         cudaFuncAttributeMaxDynamicSharedMemorySize, GEMM_SMEM);
    cudaFuncSetAttribute(kv_accum_kernel,
                         cudaFuncAttributeMaxDynamicSharedMemorySize, KV_SMEM);
    cudaFuncSetAttribute(attn_mma_kernel,
                         cudaFuncAttributeMaxDynamicSharedMemorySize, ATT_SMEM);

    // launch 0: prep (x->fp16 + RoPE tables)
    prep_kernel<<<XH_BLOCKS + RT_BLOCKS, 256>>>(x);
    // launch 1: weight transposes -> fp16
    transpose_half_kernel<<<dim3(NKV/32 + D_/32, D_/32), dim3(32, 8)>>>(Wqkv, Wout);

    // launch 2: qkv GEMM (fp16) + fused RoPE/elu epilogue (fp16 outputs)
    gemm_f16_kernel<<<dim3(NKV/128, BT/128), 256, GEMM_SMEM>>>(NKV, 1, xh_p, wqTh_p, nullptr);

    // launch 3,4: kv & ksum (tensorized accum; fp32 partials + reduce)
    kv_accum_kernel<<<BH*NCHUNK, 128, KV_SMEM>>>();
    kv_reduce_kernel<<<(BH*HD*HD)/256 + (BH*HD + 255)/256, 256>>>();

    // launch 5: attention epilogue via fp16 MMA -> g_attnh
    attn_mma_kernel<<<BH*32, 128, ATT_SMEM>>>();

    // launch 6: out = attn @ W_out (fp16 GEMM, fp32 out)
    gemm_f16_kernel<<<dim3(D_/128, BT/128), 256, GEMM_SMEM>>>(D_, 0, attnh_p, woTh_p, out);
}